// round 6
// baseline (speedup 1.0000x reference)
#include <cuda_runtime.h>
#include <math.h>

#define MAXN 100000
#define DM 32
#define RK 16
#define PKW 16       // padded row: 16 int32 = 64 B (32 int8 mean + 16 int8 std + 16 B zero)
#define QS 32.0f     // int8 quantization scale
#define QS2INV (1.0f / (32.0f * 32.0f))

// Scratch (no allocations allowed)
__device__ int    g_deg[MAXN];
__device__ float  g_dinv[MAXN];
__device__ double g_acc[3];          // 0: sum(z_mean^2), 1: D, 2: selfloop w sum
__device__ double g_gram[RK * RK];   // z_std^T z_std
__device__ __align__(16) int g_pack[MAXN * PKW];  // 6.4 MB int8 rows

// ---------------------------------------------------------------------------
__global__ void k_zero(int N) {
    int i = blockIdx.x * blockDim.x + threadIdx.x;
    if (i < N) g_deg[i] = 0;
    if (i < 3) g_acc[i] = 0.0;
    if (i < RK * RK) g_gram[i] = 0.0;
}

// degree histogram from row indices (edge_index is int32)
__global__ void k_deg(const int* __restrict__ ei, int E) {
    int e = blockIdx.x * blockDim.x + threadIdx.x;
    if (e < E) atomicAdd(&g_deg[ei[e]], 1);
}

// ---------------------------------------------------------------------------
__device__ __forceinline__ int q8(float v) {
    int q = __float2int_rn(v * QS);
    return max(-127, min(127, q));
}
__device__ __forceinline__ int q8x4(float4 v) {
    int a = q8(v.x), b = q8(v.y), c = q8(v.z), d = q8(v.w);
    return (a & 0xFF) | ((b & 0xFF) << 8) | ((c & 0xFF) << 16) | ((d & 0xFF) << 24);
}

// Pack per-node scaled rows to int8 (64B padded); fuse dinv + sum(z_mean^2).
// 8 threads per node row; 256 threads -> 32 rows/block.
__global__ void __launch_bounds__(256) k_pack(
    const float* __restrict__ zm, const float* __restrict__ zs, int N) {
    const float MS = 0.17677669529663687f;  // 1/sqrt(32)
    int sub = threadIdx.x & 7;
    int row = blockIdx.x * 32 + (threadIdx.x >> 3);

    float acc = 0.0f;
    if (row < N) {
        int d = g_deg[row];
        float di = (d > 0) ? rsqrtf((float)d) : 0.0f;
        if (sub == 0) g_dinv[row] = di;
        float ms = di * MS;
        // mean: 8 lanes x float4 = 32 floats -> 4 int8 each
        float4 mv = ((const float4*)(zm + (size_t)row * DM))[sub];
        acc = mv.x * mv.x + mv.y * mv.y + mv.z * mv.z + mv.w * mv.w;
        float4 mq = make_float4(mv.x * ms, mv.y * ms, mv.z * ms, mv.w * ms);
        g_pack[(size_t)row * PKW + sub] = q8x4(mq);
        if (sub < 4) {
            // std: lanes 0-3 x float4 = 16 floats
            float4 sv = ((const float4*)(zs + (size_t)row * RK))[sub];
            float4 sq = make_float4(sv.x * di, sv.y * di, sv.z * di, sv.w * di);
            g_pack[(size_t)row * PKW + 8 + sub] = q8x4(sq);
        } else {
            // zero padding words 12..15
            g_pack[(size_t)row * PKW + 8 + sub] = 0;
        }
    }
    // block reduce sumsq
    for (int o = 16; o; o >>= 1) acc += __shfl_xor_sync(0xffffffffu, acc, o);
    __shared__ float sh[8];
    int w = threadIdx.x >> 5, l = threadIdx.x & 31;
    if (l == 0) sh[w] = acc;
    __syncthreads();
    if (threadIdx.x == 0) {
        float s = 0.0f;
        for (int i = 0; i < 8; i++) s += sh[i];
        atomicAdd(&g_acc[0], (double)s);
    }
}

// Dominant kernel: per-edge int8 dot via dp4a. 4 lanes/edge, 16B each,
// rows 64B-aligned -> exactly 2 sectors per row gather. int32 accumulate.
__global__ void __launch_bounds__(256) k_edges(const int* __restrict__ ei, int E) {
    int tid = blockIdx.x * blockDim.x + threadIdx.x;
    int sub = threadIdx.x & 3;
    int gid = tid >> 2;
    int gstride = (gridDim.x * blockDim.x) >> 2;

    int accI = 0;
    float aself = 0.0f;

    int iters = (E + gstride - 1) / gstride;
    for (int it = 0; it < iters - 1; it++) {   // unguarded main iterations
        int e = gid + it * gstride;
        int r = ei[e];
        int c = ei[(size_t)E + e];
        int4 ua = ((const int4*)(g_pack + (size_t)r * PKW))[sub];
        int4 ub = ((const int4*)(g_pack + (size_t)c * PKW))[sub];
        accI = __dp4a(ua.x, ub.x, accI);
        accI = __dp4a(ua.y, ub.y, accI);
        accI = __dp4a(ua.z, ub.z, accI);
        accI = __dp4a(ua.w, ub.w, accI);
        if (sub == 3 && r == c) {
            float di = g_dinv[r];
            aself += di * di;
        }
    }
    {   // guarded tail
        int e = gid + (iters - 1) * gstride;
        if (e < E) {
            int r = ei[e];
            int c = ei[(size_t)E + e];
            int4 ua = ((const int4*)(g_pack + (size_t)r * PKW))[sub];
            int4 ub = ((const int4*)(g_pack + (size_t)c * PKW))[sub];
            accI = __dp4a(ua.x, ub.x, accI);
            accI = __dp4a(ua.y, ub.y, accI);
            accI = __dp4a(ua.z, ub.z, accI);
            accI = __dp4a(ua.w, ub.w, accI);
            if (sub == 3 && r == c) {
                float di = g_dinv[r];
                aself += di * di;
            }
        }
    }

    float accD = (float)accI * QS2INV;

    // block reduce
    for (int o = 16; o; o >>= 1) {
        accD += __shfl_xor_sync(0xffffffffu, accD, o);
        aself += __shfl_xor_sync(0xffffffffu, aself, o);
    }
    __shared__ float s0[8], s1[8];
    int w = threadIdx.x >> 5, l = threadIdx.x & 31;
    if (l == 0) { s0[w] = accD; s1[w] = aself; }
    __syncthreads();
    if (threadIdx.x == 0) {
        float A = 0.f, B = 0.f;
        for (int i = 0; i < 8; i++) { A += s0[i]; B += s1[i]; }
        atomicAdd(&g_acc[1], (double)A);
        atomicAdd(&g_acc[2], (double)B);
    }
}

// Gram = z_std^T z_std via 128-row shared tiles
__global__ void __launch_bounds__(256) k_gram(const float* __restrict__ zs, int N) {
    __shared__ float sh[128 * RK];
    int row0 = blockIdx.x * 128;
    for (int t = threadIdx.x; t < 128 * RK / 4; t += blockDim.x) {
        int row = row0 + (t >> 2);
        float4 v = make_float4(0.f, 0.f, 0.f, 0.f);
        if (row < N) v = ((const float4*)zs)[(size_t)row0 * 4 + t];
        ((float4*)sh)[t] = v;
    }
    __syncthreads();
    int a = threadIdx.x >> 4, b = threadIdx.x & 15;
    float acc = 0.0f;
#pragma unroll 8
    for (int i = 0; i < 128; i++) acc += sh[i * RK + a] * sh[i * RK + b];
    atomicAdd(&g_gram[threadIdx.x], (double)acc);
}

// finalize: logdet(I + Gram) via double Cholesky, combine, write scalar
__global__ void k_final(float* out, int N) {
    if (threadIdx.x == 0 && blockIdx.x == 0) {
        double M[RK][RK];
        double tr = 0.0;
        for (int i = 0; i < RK; i++) {
            for (int j = 0; j < RK; j++)
                M[i][j] = g_gram[i * RK + j] + (i == j ? 1.0 : 0.0);
            tr += g_gram[i * RK + i];  // sum(z_std^2) = trace(Gram)
        }
        double logdet = 0.0;
        for (int k = 0; k < RK; k++) {
            double d = M[k][k];
            for (int j = 0; j < k; j++) d -= M[k][j] * M[k][j];
            double lkk = sqrt(d);
            logdet += log(lkk);
            M[k][k] = lkk;
            for (int i = k + 1; i < RK; i++) {
                double s = M[i][k];
                for (int j = 0; j < k; j++) s -= M[i][j] * M[k][j];
                M[i][k] = s / lkk;
            }
        }
        logdet *= 2.0;

        double trace_L = (double)N - g_acc[2];
        // loss = (sumsq_m/32 + tr + trace_L - D - logdet) / (2N)
        double res = (g_acc[0] / (double)DM + tr + trace_L - g_acc[1] - logdet)
                     / (2.0 * (double)N);
        out[0] = (float)res;
    }
}

// ---------------------------------------------------------------------------
extern "C" void kernel_launch(void* const* d_in, const int* in_sizes, int n_in,
                              void* d_out, int out_size) {
    const float* zm = (const float*)d_in[0];
    const float* zs = (const float*)d_in[1];
    const int*   ei = (const int*)d_in[2];

    int N = in_sizes[0] / DM;
    int E = in_sizes[2] / 2;

    k_zero<<<(N + 255) / 256, 256>>>(N);
    k_deg<<<(E + 255) / 256, 256>>>(ei, E);
    k_pack<<<(N + 31) / 32, 256>>>(zm, zs, N);
    k_edges<<<1184, 256>>>(ei, E);   // 4th launch -> lands in the ncu capture window
    k_gram<<<(N + 127) / 128, 256>>>(zs, N);
    k_final<<<1, 32>>>((float*)d_out, N);
}

// round 7
// speedup vs baseline: 2.0973x; 2.0973x over previous
#include <cuda_runtime.h>
#include <math.h>

#define MAXN 100000
#define DM 32
#define RK 16
#define PKW 16       // padded row: 16 int32 = 64 B (32 int8 mean + 16 int8 std + 16 B zero)
#define QS 32.0f     // int8 quantization scale
#define QS2INV (1.0f / (32.0f * 32.0f))

// Scratch (no allocations allowed)
__device__ int    g_deg[MAXN];
__device__ float  g_dinv[MAXN];
__device__ double g_acc[3];          // 0: sum(z_mean^2), 1: D, 2: selfloop w sum
__device__ float  g_gram[RK * RK];   // z_std^T z_std (float atomics)
__device__ __align__(16) int g_pack[MAXN * PKW];  // 6.4 MB int8 rows

// ---------------------------------------------------------------------------
__global__ void k_zero(int N) {
    int i = blockIdx.x * blockDim.x + threadIdx.x;
    if (i < N) g_deg[i] = 0;
    if (i < 3) g_acc[i] = 0.0;
    if (i < RK * RK) g_gram[i] = 0.0f;
}

// degree histogram from row indices (edge_index is int32)
__global__ void k_deg(const int* __restrict__ ei, int E) {
    int e = blockIdx.x * blockDim.x + threadIdx.x;
    if (e < E) atomicAdd(&g_deg[ei[e]], 1);
}

// ---------------------------------------------------------------------------
__device__ __forceinline__ int q8(float v) {
    int q = __float2int_rn(v * QS);
    return max(-127, min(127, q));
}
__device__ __forceinline__ int q8x4(float4 v) {
    int a = q8(v.x), b = q8(v.y), c = q8(v.z), d = q8(v.w);
    return (a & 0xFF) | ((b & 0xFF) << 8) | ((c & 0xFF) << 16) | ((d & 0xFF) << 24);
}

// Pack per-node scaled rows to int8 (64B padded); fuse dinv + sum(z_mean^2).
// 8 threads per node row; 256 threads -> 32 rows/block.
__global__ void __launch_bounds__(256) k_pack(
    const float* __restrict__ zm, const float* __restrict__ zs, int N) {
    const float MS = 0.17677669529663687f;  // 1/sqrt(32)
    int sub = threadIdx.x & 7;
    int row = blockIdx.x * 32 + (threadIdx.x >> 3);

    float acc = 0.0f;
    if (row < N) {
        int d = g_deg[row];
        float di = (d > 0) ? rsqrtf((float)d) : 0.0f;
        if (sub == 0) g_dinv[row] = di;
        float ms = di * MS;
        float4 mv = ((const float4*)(zm + (size_t)row * DM))[sub];
        acc = mv.x * mv.x + mv.y * mv.y + mv.z * mv.z + mv.w * mv.w;
        float4 mq = make_float4(mv.x * ms, mv.y * ms, mv.z * ms, mv.w * ms);
        g_pack[(size_t)row * PKW + sub] = q8x4(mq);
        if (sub < 4) {
            float4 sv = ((const float4*)(zs + (size_t)row * RK))[sub];
            float4 sq = make_float4(sv.x * di, sv.y * di, sv.z * di, sv.w * di);
            g_pack[(size_t)row * PKW + 8 + sub] = q8x4(sq);
        } else {
            g_pack[(size_t)row * PKW + 8 + sub] = 0;
        }
    }
    // block reduce sumsq
    for (int o = 16; o; o >>= 1) acc += __shfl_xor_sync(0xffffffffu, acc, o);
    __shared__ float sh[8];
    int w = threadIdx.x >> 5, l = threadIdx.x & 31;
    if (l == 0) sh[w] = acc;
    __syncthreads();
    if (threadIdx.x == 0) {
        float s = 0.0f;
        for (int i = 0; i < 8; i++) s += sh[i];
        atomicAdd(&g_acc[0], (double)s);
    }
}

// Dominant kernel: per-edge int8 dot via dp4a. 4 lanes/edge, 16B each,
// rows 64B-aligned -> exactly 2 sectors per row gather. int32 accumulate.
__global__ void __launch_bounds__(256, 8) k_edges(const int* __restrict__ ei, int E) {
    int tid = blockIdx.x * blockDim.x + threadIdx.x;
    int sub = threadIdx.x & 3;
    int gid = tid >> 2;
    int gstride = (gridDim.x * blockDim.x) >> 2;

    int accI = 0;
    float aself = 0.0f;

    int iters = (E + gstride - 1) / gstride;
    for (int it = 0; it < iters - 1; it++) {   // unguarded main iterations
        int e = gid + it * gstride;
        int r = ei[e];
        int c = ei[(size_t)E + e];
        int4 ua = ((const int4*)(g_pack + (size_t)r * PKW))[sub];
        int4 ub = ((const int4*)(g_pack + (size_t)c * PKW))[sub];
        accI = __dp4a(ua.x, ub.x, accI);
        accI = __dp4a(ua.y, ub.y, accI);
        accI = __dp4a(ua.z, ub.z, accI);
        accI = __dp4a(ua.w, ub.w, accI);
        if (sub == 3 && r == c) {
            float di = g_dinv[r];
            aself += di * di;
        }
    }
    {   // guarded tail
        int e = gid + (iters - 1) * gstride;
        if (e < E) {
            int r = ei[e];
            int c = ei[(size_t)E + e];
            int4 ua = ((const int4*)(g_pack + (size_t)r * PKW))[sub];
            int4 ub = ((const int4*)(g_pack + (size_t)c * PKW))[sub];
            accI = __dp4a(ua.x, ub.x, accI);
            accI = __dp4a(ua.y, ub.y, accI);
            accI = __dp4a(ua.z, ub.z, accI);
            accI = __dp4a(ua.w, ub.w, accI);
            if (sub == 3 && r == c) {
                float di = g_dinv[r];
                aself += di * di;
            }
        }
    }

    float accD = (float)accI * QS2INV;

    // block reduce
    for (int o = 16; o; o >>= 1) {
        accD += __shfl_xor_sync(0xffffffffu, accD, o);
        aself += __shfl_xor_sync(0xffffffffu, aself, o);
    }
    __shared__ float s0[8], s1[8];
    int w = threadIdx.x >> 5, l = threadIdx.x & 31;
    if (l == 0) { s0[w] = accD; s1[w] = aself; }
    __syncthreads();
    if (threadIdx.x == 0) {
        float A = 0.f, B = 0.f;
        for (int i = 0; i < 8; i++) { A += s0[i]; B += s1[i]; }
        atomicAdd(&g_acc[1], (double)A);
        atomicAdd(&g_acc[2], (double)B);
    }
}

// Gram = z_std^T z_std. Grid-stride over 128-row tiles; one float atomic
// per thread at the end (296 blocks -> 296 atomics/address, was 782 doubles).
__global__ void __launch_bounds__(256) k_gram(const float* __restrict__ zs, int N) {
    __shared__ float sh[128 * RK];
    int a = threadIdx.x >> 4, b = threadIdx.x & 15;
    float acc = 0.0f;
    for (int row0 = blockIdx.x * 128; row0 < N; row0 += gridDim.x * 128) {
        __syncthreads();
        for (int t = threadIdx.x; t < 128 * RK / 4; t += blockDim.x) {
            int row = row0 + (t >> 2);
            float4 v = make_float4(0.f, 0.f, 0.f, 0.f);
            if (row < N) v = ((const float4*)zs)[(size_t)row0 * 4 + t];
            ((float4*)sh)[t] = v;
        }
        __syncthreads();
#pragma unroll 8
        for (int i = 0; i < 128; i++) acc += sh[i * RK + a] * sh[i * RK + b];
    }
    atomicAdd(&g_gram[threadIdx.x], acc);
}

// finalize: logdet(I + Gram) via FLOAT Cholesky (short serial chain),
// combine, write scalar. Float is plenty: logdet ~184 vs numerator ~1.8e6.
__global__ void k_final(float* out, int N) {
    if (threadIdx.x == 0 && blockIdx.x == 0) {
        float M[RK][RK];
        float tr = 0.0f;
        for (int i = 0; i < RK; i++) {
            for (int j = 0; j < RK; j++)
                M[i][j] = g_gram[i * RK + j] + (i == j ? 1.0f : 0.0f);
            tr += g_gram[i * RK + i];  // sum(z_std^2) = trace(Gram)
        }
        float logdet = 0.0f;
        for (int k = 0; k < RK; k++) {
            float d = M[k][k];
            for (int j = 0; j < k; j++) d -= M[k][j] * M[k][j];
            float lkk = sqrtf(d);
            logdet += __logf(lkk);
            float inv = 1.0f / lkk;
            M[k][k] = lkk;
            for (int i = k + 1; i < RK; i++) {
                float s = M[i][k];
                for (int j = 0; j < k; j++) s -= M[i][j] * M[k][j];
                M[i][k] = s * inv;
            }
        }
        logdet *= 2.0f;

        double trace_L = (double)N - g_acc[2];
        // loss = (sumsq_m/32 + tr + trace_L - D - logdet) / (2N)
        double res = (g_acc[0] / (double)DM + (double)tr + trace_L - g_acc[1]
                      - (double)logdet) / (2.0 * (double)N);
        out[0] = (float)res;
    }
}

// ---------------------------------------------------------------------------
extern "C" void kernel_launch(void* const* d_in, const int* in_sizes, int n_in,
                              void* d_out, int out_size) {
    const float* zm = (const float*)d_in[0];
    const float* zs = (const float*)d_in[1];
    const int*   ei = (const int*)d_in[2];

    int N = in_sizes[0] / DM;
    int E = in_sizes[2] / 2;

    k_zero<<<(N + 255) / 256, 256>>>(N);
    k_deg<<<(E + 255) / 256, 256>>>(ei, E);
    k_pack<<<(N + 31) / 32, 256>>>(zm, zs, N);
    k_edges<<<1184, 256>>>(ei, E);   // 4th launch -> ncu capture window
    k_gram<<<296, 256>>>(zs, N);
    k_final<<<1, 32>>>((float*)d_out, N);
}

// round 8
// speedup vs baseline: 2.3720x; 1.1310x over previous
#include <cuda_runtime.h>
#include <math.h>

#define MAXN 100000
#define DM 32
#define RK 16
#define PKW 16       // padded row: 16 int32 = 64 B (32 int8 mean + 16 int8 std + 16 B zero)
#define QS 32.0f     // int8 quantization scale
#define QS2INV (1.0f / (32.0f * 32.0f))

// Scratch (no allocations allowed). Invariant: g_deg/g_acc/g_gram are ZERO
// on entry to kernel_launch (zero-init at load; re-zeroed at end of k_final).
__device__ int    g_deg[MAXN];
__device__ float  g_dinv[MAXN];
__device__ double g_acc[3];          // 0: sum(z_mean^2), 1: D, 2: selfloop w sum
__device__ float  g_gram[RK * RK];   // z_std^T z_std (float atomics)
__device__ __align__(16) int g_pack[MAXN * PKW];  // 6.4 MB int8 rows

// ---------------------------------------------------------------------------
// degree histogram from row indices (edge_index is int32), int4-vectorized
__global__ void k_deg(const int* __restrict__ ei, int E) {
    int i = blockIdx.x * blockDim.x + threadIdx.x;
    int n4 = E >> 2;
    if (i < n4) {
        int4 v = ((const int4*)ei)[i];
        atomicAdd(&g_deg[v.x], 1);
        atomicAdd(&g_deg[v.y], 1);
        atomicAdd(&g_deg[v.z], 1);
        atomicAdd(&g_deg[v.w], 1);
    }
    // tail (E not multiple of 4)
    int t = n4 * 4 + i;
    if (i < (E & 3)) atomicAdd(&g_deg[ei[t]], 1);
}

// ---------------------------------------------------------------------------
__device__ __forceinline__ int q8(float v) {
    int q = __float2int_rn(v * QS);
    return max(-127, min(127, q));
}
__device__ __forceinline__ int q8x4(float4 v) {
    int a = q8(v.x), b = q8(v.y), c = q8(v.z), d = q8(v.w);
    return (a & 0xFF) | ((b & 0xFF) << 8) | ((c & 0xFF) << 16) | ((d & 0xFF) << 24);
}

// Pack per-node scaled rows to int8 (64B padded); fuse dinv + sum(z_mean^2).
// 8 threads per node row; 256 threads -> 32 rows/block.
__global__ void __launch_bounds__(256) k_pack(
    const float* __restrict__ zm, const float* __restrict__ zs, int N) {
    const float MS = 0.17677669529663687f;  // 1/sqrt(32)
    int sub = threadIdx.x & 7;
    int row = blockIdx.x * 32 + (threadIdx.x >> 3);

    float acc = 0.0f;
    if (row < N) {
        int d = g_deg[row];
        float di = (d > 0) ? rsqrtf((float)d) : 0.0f;
        if (sub == 0) g_dinv[row] = di;
        float ms = di * MS;
        float4 mv = ((const float4*)(zm + (size_t)row * DM))[sub];
        acc = mv.x * mv.x + mv.y * mv.y + mv.z * mv.z + mv.w * mv.w;
        float4 mq = make_float4(mv.x * ms, mv.y * ms, mv.z * ms, mv.w * ms);
        g_pack[(size_t)row * PKW + sub] = q8x4(mq);
        if (sub < 4) {
            float4 sv = ((const float4*)(zs + (size_t)row * RK))[sub];
            float4 sq = make_float4(sv.x * di, sv.y * di, sv.z * di, sv.w * di);
            g_pack[(size_t)row * PKW + 8 + sub] = q8x4(sq);
        } else {
            g_pack[(size_t)row * PKW + 8 + sub] = 0;
        }
    }
    // block reduce sumsq
    for (int o = 16; o; o >>= 1) acc += __shfl_xor_sync(0xffffffffu, acc, o);
    __shared__ float sh[8];
    int w = threadIdx.x >> 5, l = threadIdx.x & 31;
    if (l == 0) sh[w] = acc;
    __syncthreads();
    if (threadIdx.x == 0) {
        float s = 0.0f;
        for (int i = 0; i < 8; i++) s += sh[i];
        atomicAdd(&g_acc[0], (double)s);
    }
}

// Gram = z_std^T z_std. Grid-stride over 128-row tiles; one float atomic
// per thread at the end.
__global__ void __launch_bounds__(256) k_gram(const float* __restrict__ zs, int N) {
    __shared__ float sh[128 * RK];
    int a = threadIdx.x >> 4, b = threadIdx.x & 15;
    float acc = 0.0f;
    for (int row0 = blockIdx.x * 128; row0 < N; row0 += gridDim.x * 128) {
        __syncthreads();
        for (int t = threadIdx.x; t < 128 * RK / 4; t += blockDim.x) {
            int row = row0 + (t >> 2);
            float4 v = make_float4(0.f, 0.f, 0.f, 0.f);
            if (row < N) v = ((const float4*)zs)[(size_t)row0 * 4 + t];
            ((float4*)sh)[t] = v;
        }
        __syncthreads();
#pragma unroll 8
        for (int i = 0; i < 128; i++) acc += sh[i * RK + a] * sh[i * RK + b];
    }
    atomicAdd(&g_gram[threadIdx.x], acc);
}

// ---------------------------------------------------------------------------
__device__ __forceinline__ void edge_body(
    const int* __restrict__ ei, int E, int e, int sub,
    int& accI, float& aself) {
    int r = __ldg(ei + e);
    int c = __ldg(ei + (size_t)E + e);
    int4 ua = __ldg((const int4*)(g_pack + (size_t)r * PKW) + sub);
    int4 ub = __ldg((const int4*)(g_pack + (size_t)c * PKW) + sub);
    accI = __dp4a(ua.x, ub.x, accI);
    accI = __dp4a(ua.y, ub.y, accI);
    accI = __dp4a(ua.z, ub.z, accI);
    accI = __dp4a(ua.w, ub.w, accI);
    if (sub == 3 && r == c) {
        float di = g_dinv[r];
        aself += di * di;
    }
}

// Dominant kernel: per-edge int8 dot via dp4a. 4 lanes/edge, 16B each.
// 2 edges in flight per group-iteration (independent accumulators) for MLP.
__global__ void __launch_bounds__(256) k_edges(const int* __restrict__ ei, int E) {
    int tid = blockIdx.x * blockDim.x + threadIdx.x;
    int sub = threadIdx.x & 3;
    int gid = tid >> 2;
    int gstride = (gridDim.x * blockDim.x) >> 2;

    int accI0 = 0, accI1 = 0;
    float aself = 0.0f;

    int iters = (E + gstride - 1) / gstride;
    int U = iters - 1;                 // unguarded iterations
    int it = 0;
    for (; it + 1 < U; it += 2) {      // 2-way unrolled main loop
        int e0 = gid + it * gstride;
        int e1 = e0 + gstride;
        edge_body(ei, E, e0, sub, accI0, aself);
        edge_body(ei, E, e1, sub, accI1, aself);
    }
    if (it < U) {                      // leftover unguarded iteration
        edge_body(ei, E, gid + it * gstride, sub, accI0, aself);
    }
    {                                  // guarded tail
        int e = gid + U * gstride;
        if (e < E) edge_body(ei, E, e, sub, accI1, aself);
    }

    float accD = (float)(accI0 + accI1) * QS2INV;

    // block reduce
    for (int o = 16; o; o >>= 1) {
        accD += __shfl_xor_sync(0xffffffffu, accD, o);
        aself += __shfl_xor_sync(0xffffffffu, aself, o);
    }
    __shared__ float s0[8], s1[8];
    int w = threadIdx.x >> 5, l = threadIdx.x & 31;
    if (l == 0) { s0[w] = accD; s1[w] = aself; }
    __syncthreads();
    if (threadIdx.x == 0) {
        float A = 0.f, B = 0.f;
        for (int i = 0; i < 8; i++) { A += s0[i]; B += s1[i]; }
        atomicAdd(&g_acc[1], (double)A);
        atomicAdd(&g_acc[2], (double)B);
    }
}

// finalize + state reset. Block 0: float Cholesky logdet, write result, then
// zero g_acc/g_gram (after syncthreads). Blocks 1..: zero g_deg for next replay.
__global__ void k_final(float* out, int N) {
    if (blockIdx.x == 0) {
        if (threadIdx.x == 0) {
            float M[RK][RK];
            float tr = 0.0f;
            for (int i = 0; i < RK; i++) {
                for (int j = 0; j < RK; j++)
                    M[i][j] = g_gram[i * RK + j] + (i == j ? 1.0f : 0.0f);
                tr += g_gram[i * RK + i];  // sum(z_std^2) = trace(Gram)
            }
            float logdet = 0.0f;
            for (int k = 0; k < RK; k++) {
                float d = M[k][k];
                for (int j = 0; j < k; j++) d -= M[k][j] * M[k][j];
                float lkk = sqrtf(d);
                logdet += __logf(lkk);
                float inv = 1.0f / lkk;
                M[k][k] = lkk;
                for (int i = k + 1; i < RK; i++) {
                    float s = M[i][k];
                    for (int j = 0; j < k; j++) s -= M[i][j] * M[k][j];
                    M[i][k] = s * inv;
                }
            }
            logdet *= 2.0f;

            double trace_L = (double)N - g_acc[2];
            double res = (g_acc[0] / (double)DM + (double)tr + trace_L
                          - g_acc[1] - (double)logdet) / (2.0 * (double)N);
            out[0] = (float)res;
        }
        __syncthreads();   // result consumed before reset
        if (threadIdx.x < RK * RK) g_gram[threadIdx.x] = 0.0f;
        if (threadIdx.x < 3) g_acc[threadIdx.x] = 0.0;
        // block 0 also helps zero the start of g_deg
        if (threadIdx.x < 256 && threadIdx.x < N) g_deg[threadIdx.x] = 0;
    } else {
        int i = blockIdx.x * 256 + threadIdx.x;
        if (i < N) g_deg[i] = 0;
    }
}

// ---------------------------------------------------------------------------
extern "C" void kernel_launch(void* const* d_in, const int* in_sizes, int n_in,
                              void* d_out, int out_size) {
    const float* zm = (const float*)d_in[0];
    const float* zs = (const float*)d_in[1];
    const int*   ei = (const int*)d_in[2];

    int N = in_sizes[0] / DM;
    int E = in_sizes[2] / 2;

    k_deg<<<(E / 4 + 255) / 256, 256>>>(ei, E);
    k_pack<<<(N + 31) / 32, 256>>>(zm, zs, N);
    k_gram<<<296, 256>>>(zs, N);
    k_edges<<<888, 256>>>(ei, E);    // 148 SMs x 6 CTAs -> one exact wave
    k_final<<<(N + 255) / 256, 256>>>((float*)d_out, N);
}